// round 8
// baseline (speedup 1.0000x reference)
#include <cuda_runtime.h>

#define G       4
#define NPTS    40000
#define K       64
#define D       400
#define TILE_N  128
#define DKC     16
#define NBLK    148
#define BPG     37          // accum blocks per group (NBLK/4)
#define TILES   313         // ceil(40000/128)
#define EPOCHS  10
#define AS_STR  132         // padded strides (staging conflict avoidance)
#define BS_STR  68
#define NCHUNK  (D / DKC)   // 25

// Scratch (allocation-free: __device__ globals)
__device__ float g_centroids[G * K * D];
__device__ float g_c2[G * K];
__device__ int   g_labels[G * NPTS];
__device__ float g_slab[(size_t)NBLK * K * D];   // per-block partial sums (~15 MB)
__device__ int   g_slabcnt[NBLK * K];

__device__ __forceinline__ unsigned long long pack2f(float x, float y) {
    unsigned long long r;
    asm("mov.b64 %0, {%1, %2};" : "=l"(r) : "f"(x), "f"(y));
    return r;
}
__device__ __forceinline__ void unpack2f(unsigned long long v, float& x, float& y) {
    asm("mov.b64 {%0, %1}, %2;" : "=f"(x), "=f"(y) : "l"(v));
}
// Packed dual-lane IEEE FMA: 2x FFMA throughput on sm_103a, bitwise == scalar fmaf per lane.
__device__ __forceinline__ void fma2(unsigned long long& d, unsigned long long a, unsigned long long b) {
    asm("fma.rn.f32x2 %0, %1, %2, %0;" : "+l"(d) : "l"(a), "l"(b));
}

__device__ __forceinline__ float block_reduce_sum_128(float v) {
    __shared__ float ws[4];
    #pragma unroll
    for (int o = 16; o > 0; o >>= 1) v += __shfl_down_sync(0xffffffffu, v, o);
    if ((threadIdx.x & 31) == 0) ws[threadIdx.x >> 5] = v;
    __syncthreads();
    float r = 0.f;
    if (threadIdx.x == 0) r = ws[0] + ws[1] + ws[2] + ws[3];
    return r;
}

// Copy initial centroids into working buffer + compute 0.5*||c||^2
__global__ void init_kernel(const float* __restrict__ cinit) {
    const int b = blockIdx.x;          // g*K + k
    const int tid = threadIdx.x;       // 128 threads
    const float* src = cinit + (size_t)b * D;
    float s = 0.f;
    for (int d = tid; d < D; d += 128) {
        float v = src[d];
        g_centroids[(size_t)b * D + d] = v;
        s += v * v;
    }
    s = block_reduce_sum_128(s);
    if (tid == 0) g_c2[b] = 0.5f * s;
}

// ───────────────────────────────────────────────────────────────────────────
// Kernel 1: scores GEMM (f32x2 packed FMA, double-buffered smem) + register
// argmax via shfl butterfly -> labels to gmem. 26KB smem, 2 CTAs/SM.
// ───────────────────────────────────────────────────────────────────────────
__global__ __launch_bounds__(256, 2)
void score_kernel(const float* __restrict__ patches) {
    __shared__ float As[2][DKC * AS_STR];
    __shared__ float Bs[2][DKC * BS_STR];
    __shared__ float c2s[K];

    const int b   = blockIdx.x;        // t*4 + g : group-partners adjacent (L2 share)
    const int g   = b & 3;
    const int t   = b >> 2;
    const int tid = threadIdx.x;
    const int tx  = tid & 15;          // centroid micro-dim (16 x 4 = 64)
    const int ty  = tid >> 4;          // patch micro-dim   (16 x 8 = 128)
    const int lp  = tid >> 2;          // staging row 0..63
    const int lq  = tid & 3;           // staging quad 0..3

    const int n0   = t * TILE_N;
    const int nrem = min(TILE_N, NPTS - n0);

    if (tid < K) c2s[tid] = g_c2[g * K + tid];

    const float* Bsrc = g_centroids + (size_t)(g * K + lp) * D + lq * 4;
    const float* A0src = (lp < nrem)
        ? (patches + ((size_t)(n0 + lp) * G + g) * D + lq * 4) : (const float*)0;
    const float* A1src = (lp + 64 < nrem)
        ? (patches + ((size_t)(n0 + lp + 64) * G + g) * D + lq * 4) : (const float*)0;

    // prologue: chunk 0 -> buffer 0
    float4 ra0 = A0src ? *(const float4*)A0src : make_float4(0.f, 0.f, 0.f, 0.f);
    float4 ra1 = A1src ? *(const float4*)A1src : make_float4(0.f, 0.f, 0.f, 0.f);
    float4 rb  = *(const float4*)Bsrc;
    {
        float* a = As[0]; float* bb = Bs[0];
        a[(lq * 4 + 0) * AS_STR + lp] = ra0.x;
        a[(lq * 4 + 1) * AS_STR + lp] = ra0.y;
        a[(lq * 4 + 2) * AS_STR + lp] = ra0.z;
        a[(lq * 4 + 3) * AS_STR + lp] = ra0.w;
        a[(lq * 4 + 0) * AS_STR + lp + 64] = ra1.x;
        a[(lq * 4 + 1) * AS_STR + lp + 64] = ra1.y;
        a[(lq * 4 + 2) * AS_STR + lp + 64] = ra1.z;
        a[(lq * 4 + 3) * AS_STR + lp + 64] = ra1.w;
        bb[(lq * 4 + 0) * BS_STR + lp] = rb.x;
        bb[(lq * 4 + 1) * BS_STR + lp] = rb.y;
        bb[(lq * 4 + 2) * BS_STR + lp] = rb.z;
        bb[(lq * 4 + 3) * BS_STR + lp] = rb.w;
    }
    __syncthreads();   // c2s + buffer0 ready

    // acc[i][j]: packed pair of patches (ty*8+2i, ty*8+2i+1) vs centroid tx*4+j.
    // Init with -0.5*||c||^2 so argmax(scores) needs no epilogue subtract.
    unsigned long long acc[4][4];
    #pragma unroll
    for (int j = 0; j < 4; j++) {
        float nc = -c2s[tx * 4 + j];
        unsigned long long pv = pack2f(nc, nc);
        #pragma unroll
        for (int i = 0; i < 4; i++) acc[i][j] = pv;
    }

    #pragma unroll 1
    for (int c = 0; c < NCHUNK; ++c) {
        // prefetch next chunk global -> regs (hidden under this chunk's FMAs)
        if (c + 1 < NCHUNK) {
            const int off = (c + 1) * DKC;
            ra0 = A0src ? *(const float4*)(A0src + off) : make_float4(0.f, 0.f, 0.f, 0.f);
            ra1 = A1src ? *(const float4*)(A1src + off) : make_float4(0.f, 0.f, 0.f, 0.f);
            rb  = *(const float4*)(Bsrc + off);
        }
        const float* a = As[c & 1];
        const float* bb = Bs[c & 1];
        #pragma unroll
        for (int kk = 0; kk < DKC; kk++) {
            const float4 a0 = *(const float4*)(a + kk * AS_STR + ty * 8);
            const float4 a1 = *(const float4*)(a + kk * AS_STR + ty * 8 + 4);
            const float4 bv = *(const float4*)(bb + kk * BS_STR + tx * 4);
            unsigned long long ap[4], bd[4];
            ap[0] = pack2f(a0.x, a0.y);
            ap[1] = pack2f(a0.z, a0.w);
            ap[2] = pack2f(a1.x, a1.y);
            ap[3] = pack2f(a1.z, a1.w);
            bd[0] = pack2f(bv.x, bv.x);
            bd[1] = pack2f(bv.y, bv.y);
            bd[2] = pack2f(bv.z, bv.z);
            bd[3] = pack2f(bv.w, bv.w);
            #pragma unroll
            for (int i = 0; i < 4; i++)
                #pragma unroll
                for (int j = 0; j < 4; j++)
                    fma2(acc[i][j], ap[i], bd[j]);
        }
        // stage next chunk into the other buffer
        if (c + 1 < NCHUNK) {
            float* an = As[(c + 1) & 1]; float* bn = Bs[(c + 1) & 1];
            an[(lq * 4 + 0) * AS_STR + lp] = ra0.x;
            an[(lq * 4 + 1) * AS_STR + lp] = ra0.y;
            an[(lq * 4 + 2) * AS_STR + lp] = ra0.z;
            an[(lq * 4 + 3) * AS_STR + lp] = ra0.w;
            an[(lq * 4 + 0) * AS_STR + lp + 64] = ra1.x;
            an[(lq * 4 + 1) * AS_STR + lp + 64] = ra1.y;
            an[(lq * 4 + 2) * AS_STR + lp + 64] = ra1.z;
            an[(lq * 4 + 3) * AS_STR + lp + 64] = ra1.w;
            bn[(lq * 4 + 0) * BS_STR + lp] = rb.x;
            bn[(lq * 4 + 1) * BS_STR + lp] = rb.y;
            bn[(lq * 4 + 2) * BS_STR + lp] = rb.z;
            bn[(lq * 4 + 3) * BS_STR + lp] = rb.w;
            __syncthreads();   // writes to buf[(c+1)&1] done before next compute
        }
    }

    // Register argmax: local first-max over this thread's 4 centroids, then a
    // 16-lane shfl_xor butterfly (tx lanes are lanes 0-15 / 16-31 of a warp).
    // Merge = lexicographic max on (value, -k): equal values keep smaller k,
    // reproducing jnp.argmax first-occurrence ties. Associative + idempotent.
    #pragma unroll
    for (int i = 0; i < 4; i++) {
        float v0[4], v1[4];
        #pragma unroll
        for (int j = 0; j < 4; j++) unpack2f(acc[i][j], v0[j], v1[j]);
        float b0 = v0[0], b1 = v1[0];
        int   k0 = tx * 4, k1 = tx * 4;
        #pragma unroll
        for (int j = 1; j < 4; j++) {
            if (v0[j] > b0) { b0 = v0[j]; k0 = tx * 4 + j; }
            if (v1[j] > b1) { b1 = v1[j]; k1 = tx * 4 + j; }
        }
        #pragma unroll
        for (int o = 1; o < 16; o <<= 1) {
            float ov0 = __shfl_xor_sync(0xffffffffu, b0, o);
            int   ok0 = __shfl_xor_sync(0xffffffffu, k0, o);
            float ov1 = __shfl_xor_sync(0xffffffffu, b1, o);
            int   ok1 = __shfl_xor_sync(0xffffffffu, k1, o);
            if (ov0 > b0 || (ov0 == b0 && ok0 < k0)) { b0 = ov0; k0 = ok0; }
            if (ov1 > b1 || (ov1 == b1 && ok1 < k1)) { b1 = ov1; k1 = ok1; }
        }
        if (tx == 0) {
            const int p0 = ty * 8 + 2 * i;
            if (p0 < nrem)     g_labels[g * NPTS + n0 + p0]     = k0;
            if (p0 + 1 < nrem) g_labels[g * NPTS + n0 + p0 + 1] = k1;
        }
    }
}

// ───────────────────────────────────────────────────────────────────────────
// Kernel 2: privatized label-scatter. 148 blocks (1/SM), 100KB smem partial
// sums, no barriers in the hot loop, no float atomics -> deterministic.
// ───────────────────────────────────────────────────────────────────────────
__global__ __launch_bounds__(256, 1)
void accum_kernel(const float* __restrict__ patches) {
    extern __shared__ float part[];              // K*D
    __shared__ int cnt[K];

    const int b   = blockIdx.x;
    const int g   = b & 3;
    const int bg  = b >> 2;
    const int tid = threadIdx.x;

    for (int i = tid; i < K * D; i += 256) part[i] = 0.f;
    if (tid < K) cnt[tid] = 0;
    __syncthreads();

    for (int t = bg; t < TILES; t += BPG) {
        const int n0 = t * TILE_N;
        const int nrem = min(TILE_N, NPTS - n0);
        int p = 0;
        for (; p + 1 < nrem; p += 2) {
            const int l0 = g_labels[g * NPTS + n0 + p];
            const int l1 = g_labels[g * NPTS + n0 + p + 1];
            const float* prow0 = patches + ((size_t)(n0 + p    ) * G + g) * D;
            const float* prow1 = patches + ((size_t)(n0 + p + 1) * G + g) * D;
            float v0a = prow0[tid];
            float v1a = prow1[tid];
            float v0b = 0.f, v1b = 0.f;
            if (tid < D - 256) { v0b = prow0[tid + 256]; v1b = prow1[tid + 256]; }
            float* dst0 = part + l0 * D;
            float* dst1 = part + l1 * D;
            dst0[tid] += v0a;
            if (tid < D - 256) dst0[tid + 256] += v0b;
            dst1[tid] += v1a;
            if (tid < D - 256) dst1[tid + 256] += v1b;
        }
        if (p < nrem) {
            const int l = g_labels[g * NPTS + n0 + p];
            const float* prow = patches + ((size_t)(n0 + p) * G + g) * D;
            float* dst = part + l * D;
            dst[tid] += prow[tid];
            if (tid < D - 256) dst[tid + 256] += prow[tid + 256];
        }
    }

    // counts (integer shared atomics: deterministic; labels L2-hot)
    for (int t = bg; t < TILES; t += BPG) {
        const int n0 = t * TILE_N;
        const int nrem = min(TILE_N, NPTS - n0);
        for (int p = tid; p < nrem; p += 256)
            atomicAdd(&cnt[g_labels[g * NPTS + n0 + p]], 1);
    }
    __syncthreads();

    for (int i = tid; i < K * D; i += 256) g_slab[(size_t)b * (K * D) + i] = part[i];
    if (tid < K) g_slabcnt[b * K + tid] = cnt[tid];
}

// Deterministic slab reduction + centroid update (+ empty-cluster rule) + next c2.
__global__ void update_kernel() {
    const int b = blockIdx.x;        // g*K + k
    const int g = b >> 6;
    const int k = b & 63;
    const int tid = threadIdx.x;     // 128 threads
    __shared__ int scnt[G];
    if (tid < G) {
        int c = 0;
        for (int j = 0; j < BPG; j++) c += g_slabcnt[(tid + 4 * j) * K + k];
        scnt[tid] = c;
    }
    __syncthreads();
    const bool bad = (scnt[0] == 0) | (scnt[1] == 0) | (scnt[2] == 0) | (scnt[3] == 0);
    const int cn = scnt[g];
    const float cf = (float)(cn == 0 ? 1 : cn);
    float ss = 0.f;
    for (int d = tid; d < D; d += 128) {
        float s = 0.f;
        for (int j = 0; j < BPG; j++)
            s += g_slab[(size_t)(g + 4 * j) * (K * D) + k * D + d];
        float v = bad ? 0.f : (s / cf);
        g_centroids[(size_t)b * D + d] = v;
        ss += v * v;
    }
    ss = block_reduce_sum_128(ss);
    if (tid == 0) g_c2[b] = 0.5f * ss;
}

__global__ void copy_out_kernel(float* __restrict__ out) {
    int i = blockIdx.x * 256 + threadIdx.x;
    if (i < G * K * D) out[i] = g_centroids[i];
}

extern "C" void kernel_launch(void* const* d_in, const int* in_sizes, int n_in,
                              void* d_out, int out_size) {
    const float* patches = (const float*)d_in[0];
    const float* cinit   = (const float*)d_in[1];
    if (n_in >= 2 && in_sizes[0] == G * K * D && in_sizes[1] != G * K * D) {
        patches = (const float*)d_in[1];
        cinit   = (const float*)d_in[0];
    }
    float* out = (float*)d_out;

    const int ACC_SMEM = K * D * 4;  // 102400
    cudaFuncSetAttribute(accum_kernel, cudaFuncAttributeMaxDynamicSharedMemorySize, ACC_SMEM);

    init_kernel<<<G * K, 128>>>(cinit);
    for (int e = 0; e < EPOCHS; e++) {
        score_kernel<<<G * TILES, 256>>>(patches);
        accum_kernel<<<NBLK, 256, ACC_SMEM>>>(patches);
        update_kernel<<<G * K, 128>>>();
    }
    copy_out_kernel<<<(G * K * D + 255) / 256, 256>>>(out);
}

// round 10
// speedup vs baseline: 1.5788x; 1.5788x over previous
#include <cuda_runtime.h>

#define G       4
#define NPTS    40000
#define K       64
#define D       400
#define TILE_N  128
#define DKC     16
#define NBLK    148
#define BPG     37          // blocks per group (NBLK/4)
#define TILES   313         // ceil(40000/128)
#define EPOCHS  10
#define AS_STR  132         // padded strides (staging conflict avoidance)
#define BS_STR  68
#define NCHUNK  (D / DKC)   // 25
#define NTHREADS 512

// Scratch (allocation-free: __device__ globals)
__device__ float g_centroids[G * K * D];
__device__ float g_c2[G * K];
__device__ float g_slab[(size_t)NBLK * K * D];   // per-block partial sums (~15 MB)
__device__ int   g_slabcnt[NBLK * K];

__device__ __forceinline__ unsigned long long pack2f(float x, float y) {
    unsigned long long r;
    asm("mov.b64 %0, {%1, %2};" : "=l"(r) : "f"(x), "f"(y));
    return r;
}
__device__ __forceinline__ void unpack2f(unsigned long long v, float& x, float& y) {
    asm("mov.b64 {%0, %1}, %2;" : "=f"(x), "=f"(y) : "l"(v));
}
// Packed dual-lane IEEE FMA: 2x FFMA throughput on sm_103a, bitwise == scalar fmaf per lane.
__device__ __forceinline__ void fma2(unsigned long long& d, unsigned long long a, unsigned long long b) {
    asm("fma.rn.f32x2 %0, %1, %2, %0;" : "+l"(d) : "l"(a), "l"(b));
}

__device__ __forceinline__ float block_reduce_sum_128(float v) {
    __shared__ float ws[4];
    #pragma unroll
    for (int o = 16; o > 0; o >>= 1) v += __shfl_down_sync(0xffffffffu, v, o);
    if ((threadIdx.x & 31) == 0) ws[threadIdx.x >> 5] = v;
    __syncthreads();
    float r = 0.f;
    if (threadIdx.x == 0) r = ws[0] + ws[1] + ws[2] + ws[3];
    return r;
}

// Copy initial centroids into working buffer + compute 0.5*||c||^2
__global__ void init_kernel(const float* __restrict__ cinit) {
    const int b = blockIdx.x;          // g*K + k
    const int tid = threadIdx.x;       // 128 threads
    const float* src = cinit + (size_t)b * D;
    float s = 0.f;
    for (int d = tid; d < D; d += 128) {
        float v = src[d];
        g_centroids[(size_t)b * D + d] = v;
        s += v * v;
    }
    s = block_reduce_sum_128(s);
    if (tid == 0) g_c2[b] = 0.5f * s;
}

// ───────────────────────────────────────────────────────────────────────────
// Fused hot kernel, 512 threads (16 warps/SM): per tile
//   GEMM (f32x2 FMA, k-packed pairs, double-buffered smem)
//   -> register argmax (shfl butterfly) -> labels in smem
//   -> fused accumulate into private smem sums (patch rows L1/L2-hot).
// One block per SM; no float atomics anywhere -> deterministic.
// ───────────────────────────────────────────────────────────────────────────
__global__ __launch_bounds__(NTHREADS, 1)
void assign_kernel(const float* __restrict__ patches) {
    extern __shared__ float sm[];
    float* part = sm;                           // K*D         (100KB)
    float* As   = part + K * D;                 // 2*DKC*AS_STR
    float* Bs   = As + 2 * DKC * AS_STR;        // 2*DKC*BS_STR
    float* c2s  = Bs + 2 * DKC * BS_STR;        // K
    int* labels = (int*)(c2s + K);              // TILE_N
    __shared__ int cnt[K];

    const int b   = blockIdx.x;
    const int g   = b & 3;
    const int bg  = b >> 2;
    const int tid = threadIdx.x;
    const int tx  = tid & 15;       // centroid micro-dim: k = tx*4 + j
    const int ty  = tid >> 4;       // patch micro-dim (0..31): p = ty*4 + i
    const int lp  = tid >> 2;       // staging row 0..127
    const int lq  = tid & 3;        // staging quad 0..3

    for (int i = tid; i < K * D; i += NTHREADS) part[i] = 0.f;
    if (tid < K) { cnt[tid] = 0; c2s[tid] = g_c2[g * K + tid]; }
    __syncthreads();

    const float* Bsrc = (lp < K)
        ? (g_centroids + (size_t)(g * K + lp) * D + lq * 4) : (const float*)0;

#define STAGE(bufi, ra, rb) do {                                            \
        float* a_ = As + (bufi) * (DKC * AS_STR);                           \
        a_[(lq * 4 + 0) * AS_STR + lp] = (ra).x;                            \
        a_[(lq * 4 + 1) * AS_STR + lp] = (ra).y;                            \
        a_[(lq * 4 + 2) * AS_STR + lp] = (ra).z;                            \
        a_[(lq * 4 + 3) * AS_STR + lp] = (ra).w;                            \
        if (lp < K) {                                                       \
            float* b_ = Bs + (bufi) * (DKC * BS_STR);                       \
            b_[(lq * 4 + 0) * BS_STR + lp] = (rb).x;                        \
            b_[(lq * 4 + 1) * BS_STR + lp] = (rb).y;                        \
            b_[(lq * 4 + 2) * BS_STR + lp] = (rb).z;                        \
            b_[(lq * 4 + 3) * BS_STR + lp] = (rb).w;                        \
        }                                                                   \
    } while (0)

    for (int t = bg; t < TILES; t += BPG) {
        const int n0   = t * TILE_N;
        const int nrem = min(TILE_N, NPTS - n0);

        const float* Asrc = (lp < nrem)
            ? (patches + ((size_t)(n0 + lp) * G + g) * D + lq * 4) : (const float*)0;

        // prologue: chunk 0 -> buffer 0
        float4 ra = Asrc ? *(const float4*)Asrc : make_float4(0.f, 0.f, 0.f, 0.f);
        float4 rb = Bsrc ? *(const float4*)Bsrc : make_float4(0.f, 0.f, 0.f, 0.f);
        STAGE(0, ra, rb);
        __syncthreads();

        // acc[i][jp]: patch ty*4+i vs packed centroid pair (tx*4+2jp, tx*4+2jp+1).
        // Seeded with -0.5*||c||^2 so argmax needs no epilogue subtract.
        unsigned long long acc[4][2];
        #pragma unroll
        for (int jp = 0; jp < 2; jp++) {
            unsigned long long pv = pack2f(-c2s[tx * 4 + 2 * jp], -c2s[tx * 4 + 2 * jp + 1]);
            #pragma unroll
            for (int i = 0; i < 4; i++) acc[i][jp] = pv;
        }

        #pragma unroll 1
        for (int c = 0; c < NCHUNK; ++c) {
            if (c + 1 < NCHUNK) {   // prefetch next chunk global -> regs
                const int off = (c + 1) * DKC;
                ra = Asrc ? *(const float4*)(Asrc + off) : make_float4(0.f, 0.f, 0.f, 0.f);
                rb = Bsrc ? *(const float4*)(Bsrc + off) : make_float4(0.f, 0.f, 0.f, 0.f);
            }
            const float* a_ = As + (c & 1) * (DKC * AS_STR);
            const float* b_ = Bs + (c & 1) * (DKC * BS_STR);
            #pragma unroll
            for (int kk = 0; kk < DKC; kk++) {
                const float4 av = *(const float4*)(a_ + kk * AS_STR + ty * 4);
                const float4 bv = *(const float4*)(b_ + kk * BS_STR + tx * 4);
                unsigned long long ap[4], bd[2];
                ap[0] = pack2f(av.x, av.x);
                ap[1] = pack2f(av.y, av.y);
                ap[2] = pack2f(av.z, av.z);
                ap[3] = pack2f(av.w, av.w);
                bd[0] = pack2f(bv.x, bv.y);   // native k-pair: no duplication movs
                bd[1] = pack2f(bv.z, bv.w);
                #pragma unroll
                for (int i = 0; i < 4; i++)
                    #pragma unroll
                    for (int jp = 0; jp < 2; jp++)
                        fma2(acc[i][jp], ap[i], bd[jp]);
            }
            if (c + 1 < NCHUNK) {
                STAGE((c + 1) & 1, ra, rb);
                __syncthreads();
            }
        }

        // Register argmax per patch: local first-max over this thread's 4 k,
        // then 16-lane shfl_xor butterfly across tx (lanes 0-15 / 16-31).
        // Merge = lexicographic max on (value, smaller k): reproduces
        // jnp.argmax first-occurrence ties. Associative + idempotent.
        #pragma unroll
        for (int i = 0; i < 4; i++) {
            float v[4];
            unpack2f(acc[i][0], v[0], v[1]);
            unpack2f(acc[i][1], v[2], v[3]);
            float bb = v[0];
            int   bk = tx * 4;
            #pragma unroll
            for (int j = 1; j < 4; j++)
                if (v[j] > bb) { bb = v[j]; bk = tx * 4 + j; }
            #pragma unroll
            for (int o = 1; o < 16; o <<= 1) {
                float ov = __shfl_xor_sync(0xffffffffu, bb, o);
                int   ok = __shfl_xor_sync(0xffffffffu, bk, o);
                if (ov > bb || (ov == bb && ok < bk)) { bb = ov; bk = ok; }
            }
            if (tx == 0) {
                const int p = ty * 4 + i;
                if (p < nrem) { labels[p] = bk; atomicAdd(&cnt[bk], 1); }
            }
        }
        __syncthreads();

        // Fused accumulate: patch rows just streamed by the GEMM (L1/L2-hot).
        // 2 patches/iter, loads hoisted before the smem RMWs (MLP).
        {
            int p = 0;
            for (; p + 1 < nrem; p += 2) {
                const int l0 = labels[p];
                const int l1 = labels[p + 1];
                if (tid < D) {
                    const float v0 = patches[((size_t)(n0 + p    ) * G + g) * D + tid];
                    const float v1 = patches[((size_t)(n0 + p + 1) * G + g) * D + tid];
                    part[l0 * D + tid] += v0;
                    part[l1 * D + tid] += v1;
                }
            }
            if (p < nrem && tid < D)
                part[labels[p] * D + tid] += patches[((size_t)(n0 + p) * G + g) * D + tid];
        }
        __syncthreads();
    }
#undef STAGE

    for (int i = tid; i < K * D; i += NTHREADS) g_slab[(size_t)b * (K * D) + i] = part[i];
    if (tid < K) g_slabcnt[b * K + tid] = cnt[tid];
}

// Deterministic slab reduction + centroid update (+ empty-cluster rule) + next c2.
__global__ void update_kernel() {
    const int b = blockIdx.x;        // g*K + k
    const int g = b >> 6;
    const int k = b & 63;
    const int tid = threadIdx.x;     // 128 threads
    __shared__ int scnt[G];
    if (tid < G) {
        int c = 0;
        for (int j = 0; j < BPG; j++) c += g_slabcnt[(tid + 4 * j) * K + k];
        scnt[tid] = c;
    }
    __syncthreads();
    const bool bad = (scnt[0] == 0) | (scnt[1] == 0) | (scnt[2] == 0) | (scnt[3] == 0);
    const int cn = scnt[g];
    const float cf = (float)(cn == 0 ? 1 : cn);
    float ss = 0.f;
    for (int d = tid; d < D; d += 128) {
        float s = 0.f;
        for (int j = 0; j < BPG; j++)
            s += g_slab[(size_t)(g + 4 * j) * (K * D) + k * D + d];
        float v = bad ? 0.f : (s / cf);
        g_centroids[(size_t)b * D + d] = v;
        ss += v * v;
    }
    ss = block_reduce_sum_128(ss);
    if (tid == 0) g_c2[b] = 0.5f * ss;
}

__global__ void copy_out_kernel(float* __restrict__ out) {
    int i = blockIdx.x * 256 + threadIdx.x;
    if (i < G * K * D) out[i] = g_centroids[i];
}

extern "C" void kernel_launch(void* const* d_in, const int* in_sizes, int n_in,
                              void* d_out, int out_size) {
    const float* patches = (const float*)d_in[0];
    const float* cinit   = (const float*)d_in[1];
    if (n_in >= 2 && in_sizes[0] == G * K * D && in_sizes[1] != G * K * D) {
        patches = (const float*)d_in[1];
        cinit   = (const float*)d_in[0];
    }
    float* out = (float*)d_out;

    const int SMEM_BYTES =
        (K * D + 2 * DKC * AS_STR + 2 * DKC * BS_STR + K + TILE_N) * 4; // 128768
    cudaFuncSetAttribute(assign_kernel, cudaFuncAttributeMaxDynamicSharedMemorySize, SMEM_BYTES);

    init_kernel<<<G * K, 128>>>(cinit);
    for (int e = 0; e < EPOCHS; e++) {
        assign_kernel<<<NBLK, NTHREADS, SMEM_BYTES>>>(patches);
        update_kernel<<<G * K, 128>>>();
    }
    copy_out_kernel<<<(G * K * D + 255) / 256, 256>>>(out);
}

// round 11
// speedup vs baseline: 1.6878x; 1.0690x over previous
#include <cuda_runtime.h>

#define G       4
#define NPTS    40000
#define K       64
#define D       400
#define TILE_N  256
#define DKC     16
#define NBLK    148
#define BPG     37          // blocks per group (NBLK/4)
#define TILES   157         // ceil(40000/256)
#define EPOCHS  10
#define AS2     264         // A staging stride (floats): TILE_N + pad
#define BS2     68          // B staging stride
#define NCHUNK  (D / DKC)   // 25
#define NTHREADS 256

// Scratch (allocation-free: __device__ globals)
__device__ float g_centroids[G * K * D];
__device__ float g_c2[G * K];
__device__ float g_slab[(size_t)NBLK * K * D];   // per-block partial sums (~15 MB)
__device__ int   g_slabcnt[NBLK * K];

__device__ __forceinline__ unsigned long long pack2f(float x, float y) {
    unsigned long long r;
    asm("mov.b64 %0, {%1, %2};" : "=l"(r) : "f"(x), "f"(y));
    return r;
}
__device__ __forceinline__ void unpack2f(unsigned long long v, float& x, float& y) {
    asm("mov.b64 {%0, %1}, %2;" : "=f"(x), "=f"(y) : "l"(v));
}
// Packed dual-lane IEEE FMA: 2x FFMA throughput on sm_103a, bitwise == scalar fmaf per lane.
__device__ __forceinline__ void fma2(unsigned long long& d, unsigned long long a, unsigned long long b) {
    asm("fma.rn.f32x2 %0, %1, %2, %0;" : "+l"(d) : "l"(a), "l"(b));
}

__device__ __forceinline__ float block_reduce_sum_128(float v) {
    __shared__ float ws[4];
    #pragma unroll
    for (int o = 16; o > 0; o >>= 1) v += __shfl_down_sync(0xffffffffu, v, o);
    if ((threadIdx.x & 31) == 0) ws[threadIdx.x >> 5] = v;
    __syncthreads();
    float r = 0.f;
    if (threadIdx.x == 0) r = ws[0] + ws[1] + ws[2] + ws[3];
    return r;
}

// Copy initial centroids into working buffer + compute 0.5*||c||^2
__global__ void init_kernel(const float* __restrict__ cinit) {
    const int b = blockIdx.x;          // g*K + k
    const int tid = threadIdx.x;       // 128 threads
    const float* src = cinit + (size_t)b * D;
    float s = 0.f;
    for (int d = tid; d < D; d += 128) {
        float v = src[d];
        g_centroids[(size_t)b * D + d] = v;
        s += v * v;
    }
    s = block_reduce_sum_128(s);
    if (tid == 0) g_c2[b] = 0.5f * s;
}

// ───────────────────────────────────────────────────────────────────────────
// Fused hot kernel, 256 threads, 256-patch tiles, 8x8 microtile:
//   32 fma2 per 4 LDS.128 (4x the fma:LDS ratio of R10) + 32 independent
//   accumulators of ILP -> FMA pipe becomes the binding resource.
//   GEMM -> register argmax (8-lane shfl butterfly) -> fused accumulate into
//   private smem sums (patch rows L1/L2-hot). No float atomics.
// ───────────────────────────────────────────────────────────────────────────
__global__ __launch_bounds__(NTHREADS, 1)
void assign_kernel(const float* __restrict__ patches) {
    extern __shared__ float sm[];
    float* part = sm;                           // K*D (100KB)
    float* As   = part + K * D;                 // 2*DKC*AS2
    float* Bs   = As + 2 * DKC * AS2;           // 2*DKC*BS2
    float* c2s  = Bs + 2 * DKC * BS2;           // K
    int* labels = (int*)(c2s + K);              // TILE_N
    __shared__ int cnt[K];

    const int b   = blockIdx.x;
    const int g   = b & 3;
    const int bg  = b >> 2;
    const int tid = threadIdx.x;
    const int tx  = tid & 7;        // centroid micro-dim: k = tx*8 + j
    const int ty  = tid >> 3;       // patch micro-dim (0..31): p = ty*8 + i
    const int bl  = tid >> 2;       // B staging row 0..63
    const int bq  = tid & 3;        // B staging quad

    for (int i = tid; i < K * D; i += NTHREADS) part[i] = 0.f;
    if (tid < K) { cnt[tid] = 0; c2s[tid] = g_c2[g * K + tid]; }
    __syncthreads();

    const float* Bsrc = g_centroids + (size_t)(g * K + bl) * D + bq * 4;

#define STAGE(bufi, ra, rb) do {                                             \
        float* a_ = As + (bufi) * (DKC * AS2);                               \
        _Pragma("unroll")                                                    \
        for (int q_ = 0; q_ < 4; q_++) {                                     \
            a_[(q_ * 4 + 0) * AS2 + tid] = (ra)[q_].x;                       \
            a_[(q_ * 4 + 1) * AS2 + tid] = (ra)[q_].y;                       \
            a_[(q_ * 4 + 2) * AS2 + tid] = (ra)[q_].z;                       \
            a_[(q_ * 4 + 3) * AS2 + tid] = (ra)[q_].w;                       \
        }                                                                    \
        float* b_ = Bs + (bufi) * (DKC * BS2);                               \
        b_[(bq * 4 + 0) * BS2 + bl] = (rb).x;                               \
        b_[(bq * 4 + 1) * BS2 + bl] = (rb).y;                               \
        b_[(bq * 4 + 2) * BS2 + bl] = (rb).z;                               \
        b_[(bq * 4 + 3) * BS2 + bl] = (rb).w;                               \
    } while (0)

    for (int t = bg; t < TILES; t += BPG) {
        const int n0   = t * TILE_N;
        const int nrem = min(TILE_N, NPTS - n0);

        // A staging: 1 thread per patch row, 4 consecutive float4 per chunk.
        const float* Asrc = (tid < nrem)
            ? (patches + ((size_t)(n0 + tid) * G + g) * D) : (const float*)0;

        // prologue: chunk 0 -> buffer 0
        float4 ra[4], rb;
        #pragma unroll
        for (int q = 0; q < 4; q++)
            ra[q] = Asrc ? *(const float4*)(Asrc + q * 4) : make_float4(0.f, 0.f, 0.f, 0.f);
        rb = *(const float4*)Bsrc;
        STAGE(0, ra, rb);
        __syncthreads();

        // acc[i][jp]: patch ty*8+i vs packed centroid pair (tx*8+2jp, tx*8+2jp+1).
        // Seeded with -0.5*||c||^2 so argmax needs no epilogue subtract.
        unsigned long long acc[8][4];
        #pragma unroll
        for (int jp = 0; jp < 4; jp++) {
            unsigned long long pv = pack2f(-c2s[tx * 8 + 2 * jp], -c2s[tx * 8 + 2 * jp + 1]);
            #pragma unroll
            for (int i = 0; i < 8; i++) acc[i][jp] = pv;
        }

        #pragma unroll 1
        for (int c = 0; c < NCHUNK; ++c) {
            if (c + 1 < NCHUNK) {   // prefetch next chunk global -> regs
                const int off = (c + 1) * DKC;
                #pragma unroll
                for (int q = 0; q < 4; q++)
                    ra[q] = Asrc ? *(const float4*)(Asrc + off + q * 4)
                                 : make_float4(0.f, 0.f, 0.f, 0.f);
                rb = *(const float4*)(Bsrc + off);
            }
            const float* a_ = As + (c & 1) * (DKC * AS2);
            const float* b_ = Bs + (c & 1) * (DKC * BS2);
            #pragma unroll 8
            for (int kk = 0; kk < DKC; kk++) {
                const float4 a0 = *(const float4*)(a_ + kk * AS2 + ty * 8);
                const float4 a1 = *(const float4*)(a_ + kk * AS2 + ty * 8 + 4);
                const float4 b0 = *(const float4*)(b_ + kk * BS2 + tx * 8);
                const float4 b1 = *(const float4*)(b_ + kk * BS2 + tx * 8 + 4);
                unsigned long long ap[8], bd[4];
                ap[0] = pack2f(a0.x, a0.x);
                ap[1] = pack2f(a0.y, a0.y);
                ap[2] = pack2f(a0.z, a0.z);
                ap[3] = pack2f(a0.w, a0.w);
                ap[4] = pack2f(a1.x, a1.x);
                ap[5] = pack2f(a1.y, a1.y);
                ap[6] = pack2f(a1.z, a1.z);
                ap[7] = pack2f(a1.w, a1.w);
                bd[0] = pack2f(b0.x, b0.y);   // native k-pairs: no dup movs
                bd[1] = pack2f(b0.z, b0.w);
                bd[2] = pack2f(b1.x, b1.y);
                bd[3] = pack2f(b1.z, b1.w);
                #pragma unroll
                for (int i = 0; i < 8; i++)
                    #pragma unroll
                    for (int jp = 0; jp < 4; jp++)
                        fma2(acc[i][jp], ap[i], bd[jp]);
            }
            if (c + 1 < NCHUNK) {
                STAGE((c + 1) & 1, ra, rb);
                __syncthreads();
            }
        }

        // Register argmax per patch: local first-max over this thread's 8 k,
        // then 8-lane shfl_xor butterfly across tx (lane bits 0..2).
        // Merge = lexicographic max on (value, smaller k): reproduces
        // jnp.argmax first-occurrence ties. Associative + idempotent.
        #pragma unroll
        for (int i = 0; i < 8; i++) {
            float v[8];
            #pragma unroll
            for (int jp = 0; jp < 4; jp++) unpack2f(acc[i][jp], v[2 * jp], v[2 * jp + 1]);
            float bb = v[0];
            int   bk = tx * 8;
            #pragma unroll
            for (int j = 1; j < 8; j++)
                if (v[j] > bb) { bb = v[j]; bk = tx * 8 + j; }
            #pragma unroll
            for (int o = 1; o < 8; o <<= 1) {
                float ov = __shfl_xor_sync(0xffffffffu, bb, o);
                int   ok = __shfl_xor_sync(0xffffffffu, bk, o);
                if (ov > bb || (ov == bb && ok < bk)) { bb = ov; bk = ok; }
            }
            if (tx == 0) {
                const int p = ty * 8 + i;
                if (p < nrem) { labels[p] = bk; atomicAdd(&cnt[bk], 1); }
            }
        }
        __syncthreads();

        // Fused accumulate: patch rows just streamed by the GEMM (L1/L2-hot).
        // 2 patches/iter, loads hoisted before the smem RMWs (MLP).
        {
            int p = 0;
            for (; p + 1 < nrem; p += 2) {
                const int l0 = labels[p];
                const int l1 = labels[p + 1];
                const float* prow0 = patches + ((size_t)(n0 + p    ) * G + g) * D;
                const float* prow1 = patches + ((size_t)(n0 + p + 1) * G + g) * D;
                const float v0a = prow0[tid];
                const float v1a = prow1[tid];
                float v0b = 0.f, v1b = 0.f;
                if (tid < D - 256) { v0b = prow0[tid + 256]; v1b = prow1[tid + 256]; }
                float* dst0 = part + l0 * D;
                float* dst1 = part + l1 * D;
                dst0[tid] += v0a;
                if (tid < D - 256) dst0[tid + 256] += v0b;
                dst1[tid] += v1a;
                if (tid < D - 256) dst1[tid + 256] += v1b;
            }
            if (p < nrem) {
                const float* prow = patches + ((size_t)(n0 + p) * G + g) * D;
                float* dst = part + labels[p] * D;
                dst[tid] += prow[tid];
                if (tid < D - 256) dst[tid + 256] += prow[tid + 256];
            }
        }
        __syncthreads();
    }
#undef STAGE

    for (int i = tid; i < K * D; i += NTHREADS) g_slab[(size_t)b * (K * D) + i] = part[i];
    if (tid < K) g_slabcnt[b * K + tid] = cnt[tid];
}

// Deterministic slab reduction + centroid update (+ empty-cluster rule) + next c2.
__global__ void update_kernel() {
    const int b = blockIdx.x;        // g*K + k
    const int g = b >> 6;
    const int k = b & 63;
    const int tid = threadIdx.x;     // 128 threads
    __shared__ int scnt[G];
    if (tid < G) {
        int c = 0;
        for (int j = 0; j < BPG; j++) c += g_slabcnt[(tid + 4 * j) * K + k];
        scnt[tid] = c;
    }
    __syncthreads();
    const bool bad = (scnt[0] == 0) | (scnt[1] == 0) | (scnt[2] == 0) | (scnt[3] == 0);
    const int cn = scnt[g];
    const float cf = (float)(cn == 0 ? 1 : cn);
    float ss = 0.f;
    for (int d = tid; d < D; d += 128) {
        float s = 0.f;
        for (int j = 0; j < BPG; j++)
            s += g_slab[(size_t)(g + 4 * j) * (K * D) + k * D + d];
        float v = bad ? 0.f : (s / cf);
        g_centroids[(size_t)b * D + d] = v;
        ss += v * v;
    }
    ss = block_reduce_sum_128(ss);
    if (tid == 0) g_c2[b] = 0.5f * ss;
}

__global__ void copy_out_kernel(float* __restrict__ out) {
    int i = blockIdx.x * 256 + threadIdx.x;
    if (i < G * K * D) out[i] = g_centroids[i];
}

extern "C" void kernel_launch(void* const* d_in, const int* in_sizes, int n_in,
                              void* d_out, int out_size) {
    const float* patches = (const float*)d_in[0];
    const float* cinit   = (const float*)d_in[1];
    if (n_in >= 2 && in_sizes[0] == G * K * D && in_sizes[1] != G * K * D) {
        patches = (const float*)d_in[1];
        cinit   = (const float*)d_in[0];
    }
    float* out = (float*)d_out;

    const int SMEM_BYTES =
        (K * D + 2 * DKC * AS2 + 2 * DKC * BS2 + K + TILE_N) * 4; // 146176
    cudaFuncSetAttribute(assign_kernel, cudaFuncAttributeMaxDynamicSharedMemorySize, SMEM_BYTES);

    init_kernel<<<G * K, 128>>>(cinit);
    for (int e = 0; e < EPOCHS; e++) {
        assign_kernel<<<NBLK, NTHREADS, SMEM_BYTES>>>(patches);
        update_kernel<<<G * K, 128>>>();
    }
    copy_out_kernel<<<(G * K * D + 255) / 256, 256>>>(out);
}